// round 11
// baseline (speedup 1.0000x reference)
#include <cuda_runtime.h>
#include <cstdint>
#include <cstddef>

#define K27     27
#define N_DOWN  40000
#define N_UP    160000
#define C_DOWN  128
#define C_SKIP  64
#define C_CAT   192
#define C_OUT   96

// Permutations (within channel blocks):
// tau  (8-block):  stored[2j+r8]   = ch j + 4*r8        (LDS.64 pairs, conv)
// sigma(16-block): stored[4j+r16]  = ch j + 4*r16       (LDS.128 quads, deconv K)
__device__ float g_up   [(size_t)N_UP * C_DOWN];           // deconv out; cols tau-ordered
__device__ float g_downR[(size_t)N_DOWN * C_DOWN];         // tf32-RN, sigma-permuted
__device__ float g_skipR[(size_t)N_UP * C_SKIP];           // tf32-RN, tau-permuted
__device__ float g_WdT  [(size_t)K27 * C_DOWN * C_DOWN];   // [k][n][p] = Wd[k][sigma(p)][tau(n)]
__device__ float g_WcT  [(size_t)K27 * C_OUT  * C_CAT];    // [k][n][p] = Wc[k][tau(p)][n]

// ---------------------------------------------------------------------------
// Helpers
// ---------------------------------------------------------------------------
__device__ __forceinline__ uint32_t smem_u32(const void* p) {
    uint32_t a;
    asm("{ .reg .u64 t; cvta.to.shared.u64 t, %1; cvt.u32.u64 %0, t; }" : "=r"(a) : "l"(p));
    return a;
}
__device__ __forceinline__ float to_tf32(float x) {
    float r;
    asm("cvt.rn.tf32.f32 %0, %1;" : "=f"(r) : "f"(x));
    return r;
}
__device__ __forceinline__ int tau(int p) {       // stored pos -> channel (8-block)
    int j = p & 7, b = p & ~7;
    return b + ((j & 1) ? (j >> 1) + 4 : (j >> 1));
}
__device__ __forceinline__ int sigma(int p) {     // stored pos -> channel (16-block)
    return (p & ~15) + ((p & 15) >> 2) + ((p & 3) << 2);
}
__device__ __forceinline__ void red_add_v2(float* p, float x, float y) {
    asm volatile("red.global.add.v2.f32 [%0], {%1, %2};"
                 :: "l"(p), "f"(x), "f"(y) : "memory");
}
__device__ __forceinline__ void mma_tf32(float* c, float2 a01, float2 a23,
                                         float2 b01) {
    asm("mma.sync.aligned.m16n8k8.row.col.f32.tf32.tf32.f32 "
        "{%0,%1,%2,%3}, {%4,%5,%6,%7}, {%8,%9}, {%0,%1,%2,%3};"
        : "+f"(c[0]), "+f"(c[1]), "+f"(c[2]), "+f"(c[3])
        : "r"(__float_as_uint(a01.x)), "r"(__float_as_uint(a23.x)),
          "r"(__float_as_uint(a01.y)), "r"(__float_as_uint(a23.y)),
          "r"(__float_as_uint(b01.x)), "r"(__float_as_uint(b01.y)));
}
__device__ __forceinline__ void cp_async16(uint32_t dst, const void* src) {
    asm volatile("cp.async.cg.shared.global [%0], [%1], 16;" :: "r"(dst), "l"(src));
}
#define CP_COMMIT()  asm volatile("cp.async.commit_group;" ::: "memory")
#define CP_WAIT(n)   asm volatile("cp.async.wait_group %0;" :: "n"(n) : "memory")

// ---------------------------------------------------------------------------
// Fused prep kernel: zero(g_up,out) | round+sigma(down) | round+tau(skip) |
// transpose+round(Wd,Wc). Range-split grid.
// ---------------------------------------------------------------------------
#define UP_F4    ((N_UP * C_DOWN) / 4)     // 5,120,000
#define OUT_F4   ((N_UP * C_OUT) / 4)      // 3,840,000
#define ZERO_F4  (UP_F4 + OUT_F4)          // 8,960,000
#define DOWN_F16 ((N_DOWN * C_DOWN) / 16)  // 320,000
#define SKIP_F8  ((N_UP * C_SKIP) / 8)     // 1,280,000
#define WD_ELEMS (K27 * C_DOWN * C_DOWN)   // 442,368
#define WC_ELEMS (K27 * C_OUT * C_CAT)     // 497,664
#define PREP_TOT (ZERO_F4 + DOWN_F16 + SKIP_F8 + WD_ELEMS + WC_ELEMS)

__global__ void __launch_bounds__(256) prep_kernel(
    float4* __restrict__ out4,
    const float4* __restrict__ down4, const float4* __restrict__ skip4,
    const float* __restrict__ Wd, const float* __restrict__ Wc)
{
    int i = blockIdx.x * 256 + threadIdx.x;    // grid exact = PREP_TOT/256
    if (i < ZERO_F4) {
        float4 z = make_float4(0.f, 0.f, 0.f, 0.f);
        if (i < UP_F4) reinterpret_cast<float4*>(g_up)[i] = z;
        else           out4[i - UP_F4] = z;
        return;
    }
    i -= ZERO_F4;
    if (i < DOWN_F16) {                        // down: sigma (4x4 transpose per 16)
        float4 a = down4[4 * i], b = down4[4 * i + 1],
               c = down4[4 * i + 2], d = down4[4 * i + 3];
        float4* dst = (float4*)g_downR + 4 * i;
        dst[0] = make_float4(to_tf32(a.x), to_tf32(b.x), to_tf32(c.x), to_tf32(d.x));
        dst[1] = make_float4(to_tf32(a.y), to_tf32(b.y), to_tf32(c.y), to_tf32(d.y));
        dst[2] = make_float4(to_tf32(a.z), to_tf32(b.z), to_tf32(c.z), to_tf32(d.z));
        dst[3] = make_float4(to_tf32(a.w), to_tf32(b.w), to_tf32(c.w), to_tf32(d.w));
        return;
    }
    i -= DOWN_F16;
    if (i < SKIP_F8) {                         // skip: tau
        float4 a = skip4[2 * i], b = skip4[2 * i + 1];
        float4* dst = (float4*)g_skipR + 2 * i;
        dst[0] = make_float4(to_tf32(a.x), to_tf32(b.x), to_tf32(a.y), to_tf32(b.y));
        dst[1] = make_float4(to_tf32(a.z), to_tf32(b.z), to_tf32(a.w), to_tf32(b.w));
        return;
    }
    i -= SKIP_F8;
    if (i < WD_ELEMS) {
        int k = i / (C_DOWN * C_DOWN), r = i % (C_DOWN * C_DOWN);
        int n = r / C_DOWN, p = r % C_DOWN;
        g_WdT[i] = to_tf32(Wd[((size_t)k * C_DOWN + sigma(p)) * C_DOWN + tau(n)]);
    } else {
        int j = i - WD_ELEMS;
        int k = j / (C_OUT * C_CAT), r = j % (C_OUT * C_CAT);
        int n = r / C_CAT, p = r % C_CAT;
        g_WcT[j] = to_tf32(Wc[((size_t)k * C_CAT + tau(p)) * C_OUT + n]);
    }
}

__global__ void __launch_bounds__(256) relu_round_up_kernel() {
    int i = blockIdx.x * 256 + threadIdx.x;
    float4 v = reinterpret_cast<float4*>(g_up)[i];
    v.x = to_tf32(fmaxf(v.x, 0.f)); v.y = to_tf32(fmaxf(v.y, 0.f));
    v.z = to_tf32(fmaxf(v.z, 0.f)); v.w = to_tf32(fmaxf(v.w, 0.f));
    reinterpret_cast<float4*>(g_up)[i] = v;
}

// ---------------------------------------------------------------------------
// Deconv MMA: D[128,128] = A[128,128] @ WdT[k]^T. 4 K-phases of 32, dbl-buf
// cp.async. Stride 48 (%32==16 -> conflict-free LDS.128 quads via sigma).
// 256 threads, 8 warps, warp tile 32x64, c[2][8][4]=64 regs.
// Direct register scatter (red.add.v2) — no D staging.
// grid=(313,27), 2 CTAs/SM -> 16 warps/SM.
// ---------------------------------------------------------------------------
#define D_S     48
#define D_AB_F  (128 * D_S)                        // 6144
#define D_IDX_F (4 * D_AB_F)                       // 24576
#define D_SMEM  ((D_IDX_F + 256) * 4)              // 99,328 B

__global__ void __launch_bounds__(256, 2)
deconv_mma_kernel(const int* __restrict__ iin, const int* __restrict__ iout)
{
    extern __shared__ __align__(16) float sm[];
    const uint32_t sbase = smem_u32(sm);
    int* iidx = (int*)(sm + D_IDX_F);
    int* oidx = iidx + 128;

    const int tid = threadIdx.x, wid = tid >> 5, lane = tid & 31;
    const int g = lane >> 2, t4 = lane & 3;
    const int k = blockIdx.y;
    const int ebase = blockIdx.x * 128;
    const int nvalid = min(128, N_DOWN - ebase);

    const int* pin  = iin  + (size_t)k * N_DOWN + ebase;
    const int* pout = iout + (size_t)k * N_DOWN + ebase;
    if (tid < 128) {
        iidx[tid] = (tid < nvalid) ? pin[tid] : pin[0];
        oidx[tid] = (tid < nvalid) ? pout[tid] : -1;
    }
    __syncthreads();

    const char* Wk = (const char*)(g_WdT + (size_t)k * C_DOWN * C_DOWN);
    const char* Dn = (const char*)g_downR;
    const int mbase = (wid & 3) * 32;
    const int nbase = (wid >> 2) * 64;

    // Gather precompute: 4 chunks/thread for A and B (1024 chunks each)
    const int e8 = tid >> 3, sub16 = (tid & 7) * 16;
    uint32_t asrc[4], bsrc[4], cdst[4];
#pragma unroll
    for (int i = 0; i < 4; i++) {
        int e = e8 + 32 * i;
        asrc[i] = (uint32_t)iidx[e] * 512u;
        bsrc[i] = (uint32_t)e * 512u;
        cdst[i] = (uint32_t)e * (D_S * 4) + sub16;
    }

    auto issue = [&](int p, int buf) {
        uint32_t aB = sbase + buf * (D_AB_F * 4);
        uint32_t bB = sbase + (2 + buf) * (D_AB_F * 4);
        const char* as = Dn + p * 128 + sub16;
        const char* bs = Wk + p * 128 + sub16;
#pragma unroll
        for (int i = 0; i < 4; i++) cp_async16(aB + cdst[i], as + asrc[i]);
#pragma unroll
        for (int i = 0; i < 4; i++) cp_async16(bB + cdst[i], bs + bsrc[i]);
        CP_COMMIT();
    };

    issue(0, 0);

    float c[2][8][4] = {};
#pragma unroll
    for (int p = 0; p < 4; p++) {
        if (p < 3) issue(p + 1, (p + 1) & 1);
        if (p < 3) CP_WAIT(1); else CP_WAIT(0);
        __syncthreads();

        const float* Ab = sm + (p & 1) * D_AB_F + (mbase + g) * D_S + 4 * t4;
        const float* Bb = sm + (2 + (p & 1)) * D_AB_F + (nbase + g) * D_S + 4 * t4;
#pragma unroll
        for (int t = 0; t < 2; t++) {           // two k16 blocks per phase
            const int kk = t * 16;
            float4 A0[2], A8[2];
#pragma unroll
            for (int mt = 0; mt < 2; mt++) {
                A0[mt] = *(const float4*)(Ab + mt * 16 * D_S + kk);
                A8[mt] = *(const float4*)(Ab + (mt * 16 + 8) * D_S + kk);
            }
#pragma unroll
            for (int j = 0; j < 8; j++) {
                float4 Bq = *(const float4*)(Bb + j * 8 * D_S + kk);
                mma_tf32(c[0][j], make_float2(A0[0].x, A0[0].y),
                                  make_float2(A8[0].x, A8[0].y),
                                  make_float2(Bq.x, Bq.y));
                mma_tf32(c[1][j], make_float2(A0[1].x, A0[1].y),
                                  make_float2(A8[1].x, A8[1].y),
                                  make_float2(Bq.x, Bq.y));
                mma_tf32(c[0][j], make_float2(A0[0].z, A0[0].w),
                                  make_float2(A8[0].z, A8[0].w),
                                  make_float2(Bq.z, Bq.w));
                mma_tf32(c[1][j], make_float2(A0[1].z, A0[1].w),
                                  make_float2(A8[1].z, A8[1].w),
                                  make_float2(Bq.z, Bq.w));
            }
        }
        if (p < 3) __syncthreads();             // protect buffer reuse
    }

    // Direct register scatter: rows mbase+mt*16+g and +8, cols nbase+8j+2*t4
#pragma unroll
    for (int mt = 0; mt < 2; mt++) {
        int r0 = mbase + mt * 16 + g;
        int o0 = oidx[r0], o1 = oidx[r0 + 8];
        float* p0 = g_up + (size_t)o0 * C_DOWN;
        float* p1 = g_up + (size_t)o1 * C_DOWN;
#pragma unroll
        for (int j = 0; j < 8; j++) {
            int col = nbase + j * 8 + 2 * t4;
            if (o0 >= 0) red_add_v2(p0 + col, c[mt][j][0], c[mt][j][1]);
            if (o1 >= 0) red_add_v2(p1 + col, c[mt][j][2], c[mt][j][3]);
        }
    }
}

// ---------------------------------------------------------------------------
// Conv MMA: D[128,96] = relu_cat[128,192] @ WcT[k]^T. 6 K-phases of 32,
// dbl-buf cp.async. Stride 40 (tau LDS.64). 128 threads, 4 warps, warp tile
// 64x48, c[4][6][4]=96 regs. Direct register scatter. grid=(1250,27), 3 CTAs/SM.
// ---------------------------------------------------------------------------
#define C_S     40
#define C_AB_F  (128 * C_S)                        // 5120
#define C_BB_F  (96 * C_S)                         // 3840
#define C_IDX_F (2 * C_AB_F + 2 * C_BB_F)          // 17920
#define C_SMEM  ((C_IDX_F + 256) * 4)              // 72,704 B

__global__ void __launch_bounds__(128, 3)
conv_mma_kernel(const int* __restrict__ iin, const int* __restrict__ iout,
                float* __restrict__ out)
{
    extern __shared__ __align__(16) float sm[];
    const uint32_t sbase = smem_u32(sm);
    const uint32_t aB[2] = { sbase, sbase + C_AB_F * 4 };
    const uint32_t bB[2] = { sbase + 2 * C_AB_F * 4, sbase + (2 * C_AB_F + C_BB_F) * 4 };
    int* iidx = (int*)(sm + C_IDX_F);
    int* oidx = iidx + 128;

    const int tid = threadIdx.x, wid = tid >> 5, lane = tid & 31;
    const int g = lane >> 2, t4 = lane & 3;
    const int k = blockIdx.y;
    const int ebase = blockIdx.x * 128;

    const int* pin  = iin  + (size_t)k * N_UP + ebase;
    const int* pout = iout + (size_t)k * N_UP + ebase;
    iidx[tid] = pin[tid];
    oidx[tid] = pout[tid];
    __syncthreads();

    const char* Wk = (const char*)(g_WcT + (size_t)k * C_OUT * C_CAT);
    const char* Up = (const char*)g_up;
    const char* Sk = (const char*)g_skipR;
    const int mbase = (wid & 1) * 64;
    const int nbase = (wid >> 1) * 48;

    // Gather precompute: A 8 chunks, B 6 chunks per thread
    const int e8 = tid >> 3, sub16 = (tid & 7) * 16;
    uint32_t aoff[8], adst[8], boff[6], bdst[6];
#pragma unroll
    for (int i = 0; i < 8; i++) {
        int e = e8 + 16 * i;
        aoff[i] = (uint32_t)iidx[e] * 512u;
        adst[i] = (uint32_t)e * (C_S * 4) + sub16;
    }
#pragma unroll
    for (int i = 0; i < 6; i++) {
        int n = e8 + 16 * i;
        boff[i] = (uint32_t)n * (C_CAT * 4);
        bdst[i] = (uint32_t)n * (C_S * 4) + sub16;
    }

    auto issue = [&](int p, int buf) {
        if (p < 4) {
            const char* as = Up + p * 128 + sub16;
#pragma unroll
            for (int i = 0; i < 8; i++) cp_async16(aB[buf] + adst[i], as + aoff[i]);
        } else {
            const char* as = Sk + (p - 4) * 128 + sub16;
#pragma unroll
            for (int i = 0; i < 8; i++) cp_async16(aB[buf] + adst[i], as + (aoff[i] >> 1));
        }
        const char* bs = Wk + p * 128 + sub16;
#pragma unroll
        for (int i = 0; i < 6; i++) cp_async16(bB[buf] + bdst[i], bs + boff[i]);
        CP_COMMIT();
    };

    issue(0, 0);

    float c[4][6][4] = {};
#pragma unroll
    for (int p = 0; p < 6; p++) {
        if (p < 5) issue(p + 1, (p + 1) & 1);
        if (p < 5) CP_WAIT(1); else CP_WAIT(0);
        __syncthreads();

        const float* Ab = sm + (p & 1) * C_AB_F + (mbase + g) * C_S + 2 * t4;
        const float* Bb = sm + 2 * C_AB_F + (p & 1) * C_BB_F + (nbase + g) * C_S + 2 * t4;
#pragma unroll
        for (int s = 0; s < 4; s++) {
            const int kk = s * 8;
            float2 a01[4], a23[4];
#pragma unroll
            for (int mt = 0; mt < 4; mt++) {
                a01[mt] = *(const float2*)(Ab + mt * 16 * C_S + kk);
                a23[mt] = *(const float2*)(Ab + (mt * 16 + 8) * C_S + kk);
            }
#pragma unroll
            for (int j = 0; j < 6; j++) {
                float2 b01 = *(const float2*)(Bb + j * 8 * C_S + kk);
#pragma unroll
                for (int mt = 0; mt < 4; mt++)
                    mma_tf32(c[mt][j], a01[mt], a23[mt], b01);
            }
        }
        if (p < 5) __syncthreads();             // protect buffer reuse
    }

    // Direct register scatter: rows mbase+mt*16+g and +8, cols nbase+8j+2*t4
#pragma unroll
    for (int mt = 0; mt < 4; mt++) {
        int r0 = mbase + mt * 16 + g;
        float* p0 = out + (size_t)oidx[r0] * C_OUT;
        float* p1 = out + (size_t)oidx[r0 + 8] * C_OUT;
#pragma unroll
        for (int j = 0; j < 6; j++) {
            int col = nbase + j * 8 + 2 * t4;
            red_add_v2(p0 + col, c[mt][j][0], c[mt][j][1]);
            red_add_v2(p1 + col, c[mt][j][2], c[mt][j][3]);
        }
    }
}

// ---------------------------------------------------------------------------
// Final ReLU
// ---------------------------------------------------------------------------
__global__ void __launch_bounds__(256) relu_kernel(float4* __restrict__ out4) {
    int i = blockIdx.x * 256 + threadIdx.x;
    float4 v = out4[i];
    v.x = fmaxf(v.x, 0.f); v.y = fmaxf(v.y, 0.f);
    v.z = fmaxf(v.z, 0.f); v.w = fmaxf(v.w, 0.f);
    out4[i] = v;
}

// ---------------------------------------------------------------------------
// Launch
// ---------------------------------------------------------------------------
extern "C" void kernel_launch(void* const* d_in, const int* in_sizes, int n_in,
                              void* d_out, int out_size)
{
    const float* skip = nullptr; const float* down = nullptr;
    const float* Wd = nullptr;   const float* Wc = nullptr;
    const int *d_iin = nullptr, *d_iout = nullptr, *c_iin = nullptr, *c_iout = nullptr;

    for (int i = 0; i < n_in; i++) {
        int sz = in_sizes[i];
        if      (sz == N_UP * C_SKIP)         skip = (const float*)d_in[i];
        else if (sz == N_DOWN * C_DOWN)       down = (const float*)d_in[i];
        else if (sz == K27 * C_DOWN * C_DOWN) Wd   = (const float*)d_in[i];
        else if (sz == K27 * C_CAT * C_OUT)   Wc   = (const float*)d_in[i];
        else if (sz == K27 * N_DOWN) { if (!d_iin) d_iin = (const int*)d_in[i]; else d_iout = (const int*)d_in[i]; }
        else if (sz == K27 * N_UP)   { if (!c_iin) c_iin = (const int*)d_in[i]; else c_iout = (const int*)d_in[i]; }
    }
    float* out = (float*)d_out;

    cudaFuncSetAttribute(deconv_mma_kernel, cudaFuncAttributeMaxDynamicSharedMemorySize, D_SMEM);
    cudaFuncSetAttribute(conv_mma_kernel,   cudaFuncAttributeMaxDynamicSharedMemorySize, C_SMEM);

    prep_kernel<<<PREP_TOT / 256, 256>>>((float4*)out, (const float4*)down,
                                         (const float4*)skip, Wd, Wc);
    deconv_mma_kernel<<<dim3((N_DOWN + 127) / 128, K27), 256, D_SMEM>>>(d_iin, d_iout);
    relu_round_up_kernel<<<UP_F4 / 256, 256>>>();
    conv_mma_kernel<<<dim3(N_UP / 128, K27), 128, C_SMEM>>>(c_iin, c_iout, out);
    relu_kernel<<<OUT_F4 / 256, 256>>>((float4*)out);
}

// round 12
// speedup vs baseline: 1.0592x; 1.0592x over previous
#include <cuda_runtime.h>
#include <cstdint>
#include <cstddef>

#define K27     27
#define N_DOWN  40000
#define N_UP    160000
#define C_DOWN  128
#define C_SKIP  64
#define C_CAT   192
#define C_OUT   96

// Permutations (within channel blocks):
// tau  (8-block):  stored[2j+r8]   = ch j + 4*r8        (LDS.64 pairs, conv)
// sigma(16-block): stored[4j+r16]  = ch j + 4*r16       (LDS.128 quads, deconv K)
__device__ float g_up   [(size_t)N_UP * C_DOWN];           // deconv out; cols tau-ordered
__device__ float g_downR[(size_t)N_DOWN * C_DOWN];         // tf32-RN, sigma-permuted
__device__ float g_skipR[(size_t)N_UP * C_SKIP];           // tf32-RN, tau-permuted
__device__ float g_WdT  [(size_t)K27 * C_DOWN * C_DOWN];   // [k][n][p] = Wd[k][sigma(p)][tau(n)]
__device__ float g_WcT  [(size_t)K27 * C_OUT  * C_CAT];    // [k][n][p] = Wc[k][tau(p)][n]

// ---------------------------------------------------------------------------
// Helpers
// ---------------------------------------------------------------------------
__device__ __forceinline__ uint32_t smem_u32(const void* p) {
    uint32_t a;
    asm("{ .reg .u64 t; cvta.to.shared.u64 t, %1; cvt.u32.u64 %0, t; }" : "=r"(a) : "l"(p));
    return a;
}
__device__ __forceinline__ float to_tf32(float x) {
    float r;
    asm("cvt.rn.tf32.f32 %0, %1;" : "=f"(r) : "f"(x));
    return r;
}
__device__ __forceinline__ int tau(int p) {       // stored pos -> channel (8-block)
    int j = p & 7, b = p & ~7;
    return b + ((j & 1) ? (j >> 1) + 4 : (j >> 1));
}
__device__ __forceinline__ int sigma(int p) {     // stored pos -> channel (16-block)
    return (p & ~15) + ((p & 15) >> 2) + ((p & 3) << 2);
}
__device__ __forceinline__ void red_add_v4(float* p, float4 v) {
    asm volatile("red.global.add.v4.f32 [%0], {%1, %2, %3, %4};"
                 :: "l"(p), "f"(v.x), "f"(v.y), "f"(v.z), "f"(v.w) : "memory");
}
__device__ __forceinline__ void mma_tf32(float* c, float2 a01, float2 a23,
                                         float2 b01) {
    asm("mma.sync.aligned.m16n8k8.row.col.f32.tf32.tf32.f32 "
        "{%0,%1,%2,%3}, {%4,%5,%6,%7}, {%8,%9}, {%0,%1,%2,%3};"
        : "+f"(c[0]), "+f"(c[1]), "+f"(c[2]), "+f"(c[3])
        : "r"(__float_as_uint(a01.x)), "r"(__float_as_uint(a23.x)),
          "r"(__float_as_uint(a01.y)), "r"(__float_as_uint(a23.y)),
          "r"(__float_as_uint(b01.x)), "r"(__float_as_uint(b01.y)));
}
__device__ __forceinline__ void cp_async16(uint32_t dst, const void* src) {
    asm volatile("cp.async.cg.shared.global [%0], [%1], 16;" :: "r"(dst), "l"(src));
}
#define CP_COMMIT()  asm volatile("cp.async.commit_group;" ::: "memory")
#define CP_WAIT(n)   asm volatile("cp.async.wait_group %0;" :: "n"(n) : "memory")

// ---------------------------------------------------------------------------
// Fused prep kernel: zero(g_up,out) | round+sigma(down) | round+tau(skip) |
// transpose+round(Wd,Wc). Range-split grid.
// ---------------------------------------------------------------------------
#define UP_F4    ((N_UP * C_DOWN) / 4)     // 5,120,000
#define OUT_F4   ((N_UP * C_OUT) / 4)      // 3,840,000
#define ZERO_F4  (UP_F4 + OUT_F4)          // 8,960,000
#define DOWN_F16 ((N_DOWN * C_DOWN) / 16)  // 320,000
#define SKIP_F8  ((N_UP * C_SKIP) / 8)     // 1,280,000
#define WD_ELEMS (K27 * C_DOWN * C_DOWN)   // 442,368
#define WC_ELEMS (K27 * C_OUT * C_CAT)     // 497,664
#define PREP_TOT (ZERO_F4 + DOWN_F16 + SKIP_F8 + WD_ELEMS + WC_ELEMS)

__global__ void __launch_bounds__(256) prep_kernel(
    float4* __restrict__ out4,
    const float4* __restrict__ down4, const float4* __restrict__ skip4,
    const float* __restrict__ Wd, const float* __restrict__ Wc)
{
    int i = blockIdx.x * 256 + threadIdx.x;    // grid exact = PREP_TOT/256
    if (i < ZERO_F4) {
        float4 z = make_float4(0.f, 0.f, 0.f, 0.f);
        if (i < UP_F4) reinterpret_cast<float4*>(g_up)[i] = z;
        else           out4[i - UP_F4] = z;
        return;
    }
    i -= ZERO_F4;
    if (i < DOWN_F16) {                        // down: sigma (4x4 transpose per 16)
        float4 a = down4[4 * i], b = down4[4 * i + 1],
               c = down4[4 * i + 2], d = down4[4 * i + 3];
        float4* dst = (float4*)g_downR + 4 * i;
        dst[0] = make_float4(to_tf32(a.x), to_tf32(b.x), to_tf32(c.x), to_tf32(d.x));
        dst[1] = make_float4(to_tf32(a.y), to_tf32(b.y), to_tf32(c.y), to_tf32(d.y));
        dst[2] = make_float4(to_tf32(a.z), to_tf32(b.z), to_tf32(c.z), to_tf32(d.z));
        dst[3] = make_float4(to_tf32(a.w), to_tf32(b.w), to_tf32(c.w), to_tf32(d.w));
        return;
    }
    i -= DOWN_F16;
    if (i < SKIP_F8) {                         // skip: tau
        float4 a = skip4[2 * i], b = skip4[2 * i + 1];
        float4* dst = (float4*)g_skipR + 2 * i;
        dst[0] = make_float4(to_tf32(a.x), to_tf32(b.x), to_tf32(a.y), to_tf32(b.y));
        dst[1] = make_float4(to_tf32(a.z), to_tf32(b.z), to_tf32(a.w), to_tf32(b.w));
        return;
    }
    i -= SKIP_F8;
    if (i < WD_ELEMS) {
        int k = i / (C_DOWN * C_DOWN), r = i % (C_DOWN * C_DOWN);
        int n = r / C_DOWN, p = r % C_DOWN;
        g_WdT[i] = to_tf32(Wd[((size_t)k * C_DOWN + sigma(p)) * C_DOWN + tau(n)]);
    } else {
        int j = i - WD_ELEMS;
        int k = j / (C_OUT * C_CAT), r = j % (C_OUT * C_CAT);
        int n = r / C_CAT, p = r % C_CAT;
        g_WcT[j] = to_tf32(Wc[((size_t)k * C_CAT + tau(p)) * C_OUT + n]);
    }
}

__global__ void __launch_bounds__(256) relu_round_up_kernel() {
    int i = blockIdx.x * 256 + threadIdx.x;
    float4 v = reinterpret_cast<float4*>(g_up)[i];
    v.x = to_tf32(fmaxf(v.x, 0.f)); v.y = to_tf32(fmaxf(v.y, 0.f));
    v.z = to_tf32(fmaxf(v.z, 0.f)); v.w = to_tf32(fmaxf(v.w, 0.f));
    reinterpret_cast<float4*>(g_up)[i] = v;
}

// ---------------------------------------------------------------------------
// Deconv MMA: D[128,128] = A[128,128] @ WdT[k]^T. 4 K-phases of 32, dbl-buf
// cp.async with single-sync pipeline (issue-after-barrier). Stride 48
// (LDS.128 quads via sigma). 256 threads, 8 warps, warp tile 32x64,
// c[2][8][4]=64 regs. D staged at stride 132, v4 red scatter.
// grid=(313,27), 2 CTAs/SM -> 16 warps/SM.
// ---------------------------------------------------------------------------
#define D_S     48
#define D_AB_F  (128 * D_S)                        // 6144
#define D_IDX_F (4 * D_AB_F)                       // 24576
#define D_DP    132
#define D_SMEM  ((D_IDX_F + 256) * 4)              // 99,328 B

__global__ void __launch_bounds__(256, 2)
deconv_mma_kernel(const int* __restrict__ iin, const int* __restrict__ iout)
{
    extern __shared__ __align__(16) float sm[];
    const uint32_t sbase = smem_u32(sm);
    int* iidx = (int*)(sm + D_IDX_F);
    int* oidx = iidx + 128;

    const int tid = threadIdx.x, wid = tid >> 5, lane = tid & 31;
    const int g = lane >> 2, t4 = lane & 3;
    const int k = blockIdx.y;
    const int ebase = blockIdx.x * 128;
    const int nvalid = min(128, N_DOWN - ebase);

    const int* pin  = iin  + (size_t)k * N_DOWN + ebase;
    const int* pout = iout + (size_t)k * N_DOWN + ebase;
    if (tid < 128) {
        iidx[tid] = (tid < nvalid) ? pin[tid] : pin[0];
        oidx[tid] = (tid < nvalid) ? pout[tid] : -1;
    }
    __syncthreads();

    const char* Wk = (const char*)(g_WdT + (size_t)k * C_DOWN * C_DOWN);
    const char* Dn = (const char*)g_downR;
    const int mbase = (wid & 3) * 32;
    const int nbase = (wid >> 2) * 64;

    // Gather precompute: 4 chunks/thread for A and B (1024 chunks each)
    const int e8 = tid >> 3, sub16 = (tid & 7) * 16;
    uint32_t asrc[4], bsrc[4], cdst[4];
#pragma unroll
    for (int i = 0; i < 4; i++) {
        int e = e8 + 32 * i;
        asrc[i] = (uint32_t)iidx[e] * 512u;
        bsrc[i] = (uint32_t)e * 512u;
        cdst[i] = (uint32_t)e * (D_S * 4) + sub16;
    }

    auto issue = [&](int p, int buf) {
        uint32_t aB = sbase + buf * (D_AB_F * 4);
        uint32_t bB = sbase + (2 + buf) * (D_AB_F * 4);
        const char* as = Dn + p * 128 + sub16;
        const char* bs = Wk + p * 128 + sub16;
#pragma unroll
        for (int i = 0; i < 4; i++) cp_async16(aB + cdst[i], as + asrc[i]);
#pragma unroll
        for (int i = 0; i < 4; i++) cp_async16(bB + cdst[i], bs + bsrc[i]);
        CP_COMMIT();
    };

    issue(0, 0);

    float c[2][8][4] = {};
#pragma unroll
    for (int p = 0; p < 4; p++) {
        CP_WAIT(0);
        __syncthreads();            // phase-p data visible AND compute(p-1) done
        if (p < 3) issue(p + 1, (p + 1) & 1);

        const float* Ab = sm + (p & 1) * D_AB_F + (mbase + g) * D_S + 4 * t4;
        const float* Bb = sm + (2 + (p & 1)) * D_AB_F + (nbase + g) * D_S + 4 * t4;
#pragma unroll
        for (int t = 0; t < 2; t++) {           // two k16 blocks per phase
            const int kk = t * 16;
            float4 A0[2], A8[2];
#pragma unroll
            for (int mt = 0; mt < 2; mt++) {
                A0[mt] = *(const float4*)(Ab + mt * 16 * D_S + kk);
                A8[mt] = *(const float4*)(Ab + (mt * 16 + 8) * D_S + kk);
            }
#pragma unroll
            for (int j = 0; j < 8; j++) {
                float4 Bq = *(const float4*)(Bb + j * 8 * D_S + kk);
                mma_tf32(c[0][j], make_float2(A0[0].x, A0[0].y),
                                  make_float2(A8[0].x, A8[0].y),
                                  make_float2(Bq.x, Bq.y));
                mma_tf32(c[1][j], make_float2(A0[1].x, A0[1].y),
                                  make_float2(A8[1].x, A8[1].y),
                                  make_float2(Bq.x, Bq.y));
                mma_tf32(c[0][j], make_float2(A0[0].z, A0[0].w),
                                  make_float2(A8[0].z, A8[0].w),
                                  make_float2(Bq.z, Bq.w));
                mma_tf32(c[1][j], make_float2(A0[1].z, A0[1].w),
                                  make_float2(A8[1].z, A8[1].w),
                                  make_float2(Bq.z, Bq.w));
            }
        }
    }
    __syncthreads();                // all compute done before D staging reuses sm

    // Stage D (stride 132) over buffer region
#pragma unroll
    for (int mt = 0; mt < 2; mt++) {
        int row = mbase + mt * 16 + g;
#pragma unroll
        for (int j = 0; j < 8; j++) {
            int col = nbase + j * 8 + 2 * t4;
            *(float2*)&sm[row * D_DP + col]       = make_float2(c[mt][j][0], c[mt][j][1]);
            *(float2*)&sm[(row + 8) * D_DP + col] = make_float2(c[mt][j][2], c[mt][j][3]);
        }
    }
    __syncthreads();

    // Scatter: 4096 f4, 16/thread
#pragma unroll
    for (int t = 0; t < 16; t++) {
        int f = tid + t * 256;
        int e = f >> 5, q = f & 31;
        int o = oidx[e];
        if (o >= 0) {
            float4 v = *(float4*)&sm[e * D_DP + q * 4];
            red_add_v4(g_up + (size_t)o * C_DOWN + q * 4, v);
        }
    }
}

// ---------------------------------------------------------------------------
// Conv MMA: D[128,96] = relu_cat[128,192] @ WcT[k]^T. 6 K-phases of 32,
// dbl-buf cp.async, single-sync pipeline. Stride 40 (tau LDS.64). 128 threads,
// 4 warps, warp tile 64x48, c[4][6][4]=96 regs. D staged at stride 100,
// v4 red scatter. grid=(1250,27), 3 CTAs/SM -> 12 warps/SM.
// ---------------------------------------------------------------------------
#define C_S     40
#define C_AB_F  (128 * C_S)                        // 5120
#define C_BB_F  (96 * C_S)                         // 3840
#define C_IDX_F (2 * C_AB_F + 2 * C_BB_F)          // 17920
#define C_DP    100
#define C_SMEM  ((C_IDX_F + 256) * 4)              // 72,704 B

__global__ void __launch_bounds__(128, 3)
conv_mma_kernel(const int* __restrict__ iin, const int* __restrict__ iout,
                float* __restrict__ out)
{
    extern __shared__ __align__(16) float sm[];
    const uint32_t sbase = smem_u32(sm);
    const uint32_t aB[2] = { sbase, sbase + C_AB_F * 4 };
    const uint32_t bB[2] = { sbase + 2 * C_AB_F * 4, sbase + (2 * C_AB_F + C_BB_F) * 4 };
    int* iidx = (int*)(sm + C_IDX_F);
    int* oidx = iidx + 128;

    const int tid = threadIdx.x, wid = tid >> 5, lane = tid & 31;
    const int g = lane >> 2, t4 = lane & 3;
    const int k = blockIdx.y;
    const int ebase = blockIdx.x * 128;

    const int* pin  = iin  + (size_t)k * N_UP + ebase;
    const int* pout = iout + (size_t)k * N_UP + ebase;
    iidx[tid] = pin[tid];
    oidx[tid] = pout[tid];
    __syncthreads();

    const char* Wk = (const char*)(g_WcT + (size_t)k * C_OUT * C_CAT);
    const char* Up = (const char*)g_up;
    const char* Sk = (const char*)g_skipR;
    const int mbase = (wid & 1) * 64;
    const int nbase = (wid >> 1) * 48;

    // Gather precompute: A 8 chunks, B 6 chunks per thread
    const int e8 = tid >> 3, sub16 = (tid & 7) * 16;
    uint32_t aoff[8], adst[8], boff[6], bdst[6];
#pragma unroll
    for (int i = 0; i < 8; i++) {
        int e = e8 + 16 * i;
        aoff[i] = (uint32_t)iidx[e] * 512u;
        adst[i] = (uint32_t)e * (C_S * 4) + sub16;
    }
#pragma unroll
    for (int i = 0; i < 6; i++) {
        int n = e8 + 16 * i;
        boff[i] = (uint32_t)n * (C_CAT * 4);
        bdst[i] = (uint32_t)n * (C_S * 4) + sub16;
    }

    auto issue = [&](int p, int buf) {
        if (p < 4) {
            const char* as = Up + p * 128 + sub16;
#pragma unroll
            for (int i = 0; i < 8; i++) cp_async16(aB[buf] + adst[i], as + aoff[i]);
        } else {
            const char* as = Sk + (p - 4) * 128 + sub16;
#pragma unroll
            for (int i = 0; i < 8; i++) cp_async16(aB[buf] + adst[i], as + (aoff[i] >> 1));
        }
        const char* bs = Wk + p * 128 + sub16;
#pragma unroll
        for (int i = 0; i < 6; i++) cp_async16(bB[buf] + bdst[i], bs + boff[i]);
        CP_COMMIT();
    };

    issue(0, 0);

    float c[4][6][4] = {};
#pragma unroll
    for (int p = 0; p < 6; p++) {
        CP_WAIT(0);
        __syncthreads();            // phase-p data visible AND compute(p-1) done
        if (p < 5) issue(p + 1, (p + 1) & 1);

        const float* Ab = sm + (p & 1) * C_AB_F + (mbase + g) * C_S + 2 * t4;
        const float* Bb = sm + 2 * C_AB_F + (p & 1) * C_BB_F + (nbase + g) * C_S + 2 * t4;
#pragma unroll
        for (int s = 0; s < 4; s++) {
            const int kk = s * 8;
            float2 a01[4], a23[4];
#pragma unroll
            for (int mt = 0; mt < 4; mt++) {
                a01[mt] = *(const float2*)(Ab + mt * 16 * C_S + kk);
                a23[mt] = *(const float2*)(Ab + (mt * 16 + 8) * C_S + kk);
            }
#pragma unroll
            for (int j = 0; j < 6; j++) {
                float2 b01 = *(const float2*)(Bb + j * 8 * C_S + kk);
#pragma unroll
                for (int mt = 0; mt < 4; mt++)
                    mma_tf32(c[mt][j], a01[mt], a23[mt], b01);
            }
        }
    }
    __syncthreads();                // all compute done before D staging reuses sm

    // Stage D (stride 100) over buffer region
#pragma unroll
    for (int mt = 0; mt < 4; mt++) {
        int row = mbase + mt * 16 + g;
#pragma unroll
        for (int j = 0; j < 6; j++) {
            int col = nbase + j * 8 + 2 * t4;
            *(float2*)&sm[row * C_DP + col]       = make_float2(c[mt][j][0], c[mt][j][1]);
            *(float2*)&sm[(row + 8) * C_DP + col] = make_float2(c[mt][j][2], c[mt][j][3]);
        }
    }
    __syncthreads();

    // Scatter: 3072 f4, 24/thread
#pragma unroll
    for (int t = 0; t < 24; t++) {
        int f = tid + t * 128;
        int e = f / 24, q = f % 24;
        float4 v = *(float4*)&sm[e * C_DP + q * 4];
        red_add_v4(out + (size_t)oidx[e] * C_OUT + q * 4, v);
    }
}

// ---------------------------------------------------------------------------
// Final ReLU
// ---------------------------------------------------------------------------
__global__ void __launch_bounds__(256) relu_kernel(float4* __restrict__ out4) {
    int i = blockIdx.x * 256 + threadIdx.x;
    float4 v = out4[i];
    v.x = fmaxf(v.x, 0.f); v.y = fmaxf(v.y, 0.f);
    v.z = fmaxf(v.z, 0.f); v.w = fmaxf(v.w, 0.f);
    out4[i] = v;
}

// ---------------------------------------------------------------------------
// Launch
// ---------------------------------------------------------------------------
extern "C" void kernel_launch(void* const* d_in, const int* in_sizes, int n_in,
                              void* d_out, int out_size)
{
    const float* skip = nullptr; const float* down = nullptr;
    const float* Wd = nullptr;   const float* Wc = nullptr;
    const int *d_iin = nullptr, *d_iout = nullptr, *c_iin = nullptr, *c_iout = nullptr;

    for (int i = 0; i < n_in; i++) {
        int sz = in_sizes[i];
        if      (sz == N_UP * C_SKIP)         skip = (const float*)d_in[i];
        else if (sz == N_DOWN * C_DOWN)       down = (const float*)d_in[i];
        else if (sz == K27 * C_DOWN * C_DOWN) Wd   = (const float*)d_in[i];
        else if (sz == K27 * C_CAT * C_OUT)   Wc   = (const float*)d_in[i];
        else if (sz == K27 * N_DOWN) { if (!d_iin) d_iin = (const int*)d_in[i]; else d_iout = (const int*)d_in[i]; }
        else if (sz == K27 * N_UP)   { if (!c_iin) c_iin = (const int*)d_in[i]; else c_iout = (const int*)d_in[i]; }
    }
    float* out = (float*)d_out;

    cudaFuncSetAttribute(deconv_mma_kernel, cudaFuncAttributeMaxDynamicSharedMemorySize, D_SMEM);
    cudaFuncSetAttribute(conv_mma_kernel,   cudaFuncAttributeMaxDynamicSharedMemorySize, C_SMEM);

    prep_kernel<<<PREP_TOT / 256, 256>>>((float4*)out, (const float4*)down,
                                         (const float4*)skip, Wd, Wc);
    deconv_mma_kernel<<<dim3((N_DOWN + 127) / 128, K27), 256, D_SMEM>>>(d_iin, d_iout);
    relu_round_up_kernel<<<UP_F4 / 256, 256>>>();
    conv_mma_kernel<<<dim3(N_UP / 128, K27), 128, C_SMEM>>>(c_iin, c_iout, out);
    relu_kernel<<<OUT_F4 / 256, 256>>>((float4*)out);
}